// round 4
// baseline (speedup 1.0000x reference)
#include <cuda_runtime.h>
#include <cstdint>

#define BM      32
#define THREADS 512
#define NWARP   16

__device__ float  g_bfrag[128 * 8 * 32 * 4];  // [ntg][kk][lane]{hi0,hi1,lo0,lo1}
__device__ float  g_wn1[1024];                // ||e_c||^2 + 1
__device__ double g_loss;

__device__ __forceinline__ uint32_t tf32_rna(float v) {
    uint32_t u; asm("cvt.rna.tf32.f32 %0, %1;" : "=r"(u) : "f"(v));
    return u;
}
__device__ __forceinline__ float rcpf(float x) {
    float r; asm("rcp.approx.f32 %0, %1;" : "=f"(r) : "f"(x)); return r;
}
__device__ __forceinline__ unsigned int ordered_u32(float f) {
    unsigned int u = __float_as_uint(f);
    return (u & 0x80000000u) ? ~u : (u | 0x80000000u);
}
__device__ __forceinline__ void mma_tf32(float* d, const uint32_t* a,
                                         uint32_t b0, uint32_t b1) {
    asm volatile(
        "mma.sync.aligned.m16n8k8.row.col.f32.tf32.tf32.f32 "
        "{%0,%1,%2,%3}, {%4,%5,%6,%7}, {%8,%9}, {%0,%1,%2,%3};"
        : "+f"(d[0]), "+f"(d[1]), "+f"(d[2]), "+f"(d[3])
        : "r"(a[0]), "r"(a[1]), "r"(a[2]), "r"(a[3]), "r"(b0), "r"(b1));
}

// ---------------------------------------------------------------------------
// Prep: per block, 8 codebook rows staged in smem -> wn1 + tf32 hi/lo B frags
// grid 128 x 256 threads; block b handles ntg=b (rows 8b..8b+7), warp w = kk.
// ---------------------------------------------------------------------------
__global__ void vq_prep(const float* __restrict__ cb) {
    __shared__ float rows[8 * 64];
    const int tid = threadIdx.x;
    const int ntg = blockIdx.x;
    if (ntg == 0 && tid == 0) g_loss = 0.0;
    ((float2*)rows)[tid] = ((const float2*)(cb + (size_t)ntg * 8 * 64))[tid];
    __syncthreads();
    if (tid < 8) {
        float s = 0.f;
        const float* r = rows + tid * 64;
#pragma unroll 16
        for (int k = 0; k < 64; k++) { float v = r[k]; s += v * v; }
        g_wn1[ntg * 8 + tid] = s + 1.f;
    }
    const int lane = tid & 31;
    const int kk   = tid >> 5;
    const int g = lane >> 2, tq = lane & 3;
    const int k0 = kk * 8 + tq;
    float v0 = -2.f * rows[g * 64 + k0];
    float v1 = -2.f * rows[g * 64 + k0 + 4];
    uint32_t h0 = tf32_rna(v0), h1 = tf32_rna(v1);
    float4 o;
    o.x = __uint_as_float(h0);
    o.y = __uint_as_float(h1);
    o.z = __uint_as_float(tf32_rna(v0 - o.x));
    o.w = __uint_as_float(tf32_rna(v1 - o.y));
    ((float4*)g_bfrag)[(size_t)ntg * 256 + tid] = o;
}

// ---------------------------------------------------------------------------
// Main fused kernel: 32 rows x 1024 cols per CTA, tf32x3 mma.sync GEMM
// ---------------------------------------------------------------------------
__global__ void __launch_bounds__(THREADS, 1)
vq_main(const float* __restrict__ z, const float* __restrict__ cb,
        float* __restrict__ q_out, float* __restrict__ zq_out) {
    __shared__ float z_s[32 * 64];        // raw z tile
    __shared__ float ahi_s[512 * 4];      // A hi frags [kk*2+mt][lane][4]
    __shared__ float alo_s[512 * 4];      // A lo frags
    __shared__ float wn_s[1024];
    __shared__ float zn2_s[32];
    __shared__ float inv_s[32];
    __shared__ int   bc_s[32];
    __shared__ float rs_p[NWARP][32];
    __shared__ unsigned long long key_p[NWARP][32];

    const int tid  = threadIdx.x;
    const int wid  = tid >> 5;
    const int lane = tid & 31;
    const int g    = lane >> 2;
    const int tq   = lane & 3;
    const int r0   = blockIdx.x * BM;

    // stage raw z (coalesced) + wn1
    ((float4*)z_s)[tid] = ((const float4*)(z + (size_t)r0 * 64))[tid];
    wn_s[tid]       = g_wn1[tid];
    wn_s[tid + 512] = g_wn1[tid + 512];
    __syncthreads();

    // build A fragments: slot s=tid -> kk=s>>6, mt=(s>>5)&1, lane=s&31
    {
        int s_  = tid;
        int kk  = s_ >> 6, mt = (s_ >> 5) & 1, ln = s_ & 31;
        int gg = ln >> 2, qq = ln & 3;
        int rr = mt * 16 + gg, k0 = kk * 8 + qq;
        float a0 = z_s[rr * 64 + k0];
        float a1 = z_s[(rr + 8) * 64 + k0];
        float a2 = z_s[rr * 64 + k0 + 4];
        float a3 = z_s[(rr + 8) * 64 + k0 + 4];
        float4 hv, lv;
        hv.x = __uint_as_float(tf32_rna(a0));
        hv.y = __uint_as_float(tf32_rna(a1));
        hv.z = __uint_as_float(tf32_rna(a2));
        hv.w = __uint_as_float(tf32_rna(a3));
        lv.x = __uint_as_float(tf32_rna(a0 - hv.x));
        lv.y = __uint_as_float(tf32_rna(a1 - hv.y));
        lv.z = __uint_as_float(tf32_rna(a2 - hv.z));
        lv.w = __uint_as_float(tf32_rna(a3 - hv.w));
        ((float4*)ahi_s)[s_] = hv;
        ((float4*)alo_s)[s_] = lv;
    }
    if (tid < 32) {
        float s = 0.f;
        const float* zr = z_s + tid * 64;
#pragma unroll 16
        for (int k = 0; k < 64; k++) { float v = zr[k]; s += v * v; }
        zn2_s[tid] = s;
    }
    __syncthreads();

    // ---- GEMM: acc[mt][nt][4], deep B prefetch (MLP=8) ----
    float acc[2][8][4];
#pragma unroll
    for (int mt = 0; mt < 2; mt++)
#pragma unroll
        for (int nt = 0; nt < 8; nt++)
#pragma unroll
            for (int r = 0; r < 4; r++) acc[mt][nt][r] = 0.f;

    // frag (nt, kk) at bb + nt*256 + kk*32   (float4 units)
    const float4* bb = (const float4*)g_bfrag + (size_t)(wid * 64) * 32 + lane;

    float4 bf[8];
#pragma unroll
    for (int nt = 0; nt < 8; nt++) bf[nt] = __ldg(bb + nt * 256);

#pragma unroll 1
    for (int kk = 0; kk < 8; kk++) {
        uint32_t ah[2][4], al[2][4];
#pragma unroll
        for (int mt = 0; mt < 2; mt++) {
            float4 h = ((const float4*)ahi_s)[(kk * 2 + mt) * 32 + lane];
            float4 l = ((const float4*)alo_s)[(kk * 2 + mt) * 32 + lane];
            ah[mt][0] = __float_as_uint(h.x); ah[mt][1] = __float_as_uint(h.y);
            ah[mt][2] = __float_as_uint(h.z); ah[mt][3] = __float_as_uint(h.w);
            al[mt][0] = __float_as_uint(l.x); al[mt][1] = __float_as_uint(l.y);
            al[mt][2] = __float_as_uint(l.z); al[mt][3] = __float_as_uint(l.w);
        }
#pragma unroll
        for (int nt = 0; nt < 8; nt++) {
            float4 b = bf[nt];
            if (kk < 7) bf[nt] = __ldg(bb + nt * 256 + (kk + 1) * 32);
            uint32_t bh0 = __float_as_uint(b.x), bh1 = __float_as_uint(b.y);
            uint32_t bl0 = __float_as_uint(b.z), bl1 = __float_as_uint(b.w);
            mma_tf32(acc[0][nt], ah[0], bh0, bh1);
            mma_tf32(acc[1][nt], ah[1], bh0, bh1);
            mma_tf32(acc[0][nt], ah[0], bl0, bl1);
            mma_tf32(acc[1][nt], ah[1], bl0, bl1);
            mma_tf32(acc[0][nt], al[0], bh0, bh1);
            mma_tf32(acc[1][nt], al[1], bh0, bh1);
        }
    }

    // ---- epilogue: S = acc + zn2 + wn1 ; q_un = rcp(S); rowsum + argmax ----
    float rs[4] = {0.f, 0.f, 0.f, 0.f};
    unsigned long long key[4] = {0ull, 0ull, 0ull, 0ull};
    const int wc0 = wid * 64;

#pragma unroll
    for (int mt = 0; mt < 2; mt++) {
#pragma unroll
        for (int h = 0; h < 2; h++) {
            int rloc = mt * 16 + g + h * 8;
            float zn = zn2_s[rloc];
#pragma unroll
            for (int nt = 0; nt < 8; nt++) {
#pragma unroll
                for (int p = 0; p < 2; p++) {
                    int c  = wc0 + nt * 8 + tq * 2 + p;
                    float S = acc[mt][nt][h * 2 + p] + zn + wn_s[c];
                    float qv = rcpf(S);
                    acc[mt][nt][h * 2 + p] = qv;
                    rs[mt * 2 + h] += qv;
                    unsigned long long k =
                        ((unsigned long long)ordered_u32(S) << 32) |
                        (unsigned long long)(0xFFFFFFFFu - (unsigned int)c);
                    if (k > key[mt * 2 + h]) key[mt * 2 + h] = k;
                }
            }
        }
    }
    // quad reduce (lanes sharing g)
#pragma unroll
    for (int m = 1; m <= 2; m <<= 1) {
#pragma unroll
        for (int r = 0; r < 4; r++) {
            rs[r] += __shfl_xor_sync(0xFFFFFFFFu, rs[r], m);
            unsigned long long o = __shfl_xor_sync(0xFFFFFFFFu, key[r], m);
            if (o > key[r]) key[r] = o;
        }
    }
    if (tq == 0) {
#pragma unroll
        for (int r = 0; r < 4; r++) {
            int rloc = (r >> 1) * 16 + g + (r & 1) * 8;
            rs_p[wid][rloc]  = rs[r];
            key_p[wid][rloc] = key[r];
        }
    }
    __syncthreads();
    if (tid < 32) {
        float s = 0.f;
        unsigned long long bk = 0ull;
#pragma unroll
        for (int w = 0; w < NWARP; w++) {
            s += rs_p[w][tid];
            unsigned long long k = key_p[w][tid];
            if (k > bk) bk = k;
        }
        inv_s[tid] = 1.0f / s;
        bc_s[tid]  = (int)(0xFFFFFFFFu - (unsigned int)(bk & 0xFFFFFFFFull));
    }
    __syncthreads();

    // ---- store normalized q ----
#pragma unroll
    for (int mt = 0; mt < 2; mt++) {
#pragma unroll
        for (int h = 0; h < 2; h++) {
            int rloc = mt * 16 + g + h * 8;
            float inv = inv_s[rloc];
            float* base = q_out + (size_t)(r0 + rloc) * 1024 + wc0 + tq * 2;
#pragma unroll
            for (int nt = 0; nt < 8; nt++) {
                float2 v;
                v.x = acc[mt][nt][h * 2 + 0] * inv;
                v.y = acc[mt][nt][h * 2 + 1] * inv;
                *(float2*)(base + nt * 8) = v;
            }
        }
    }

    // ---- gather z_q, store, loss partial ----
    float lp;
    {
        int rr = tid >> 4, j4 = tid & 15;
        int cbest = bc_s[rr];
        float4 e  = ((const float4*)(cb + (size_t)cbest * 64))[j4];
        float4 zv = ((const float4*)z_s)[rr * 16 + j4];
        ((float4*)(zq_out + (size_t)(r0 + rr) * 64))[j4] = e;
        float dx = e.x - zv.x, dy = e.y - zv.y,
              dz = e.z - zv.z, dw = e.w - zv.w;
        lp = dx * dx + dy * dy + dz * dz + dw * dw;
    }
#pragma unroll
    for (int m = 16; m > 0; m >>= 1)
        lp += __shfl_xor_sync(0xFFFFFFFFu, lp, m);
    float* red = &rs_p[0][0];
    if (lane == 0) red[wid] = lp;
    __syncthreads();
    if (tid < 16) {
        float v = red[tid];
#pragma unroll
        for (int m = 8; m > 0; m >>= 1)
            v += __shfl_xor_sync(0x0000FFFFu, v, m);
        if (tid == 0) atomicAdd(&g_loss, (double)v);
    }
}

__global__ void vq_finalize(float* __restrict__ loss_out) {
    loss_out[0] = (float)(1.25 * g_loss / (65536.0 * 64.0));
}

extern "C" void kernel_launch(void* const* d_in, const int* in_sizes, int n_in,
                              void* d_out, int out_size) {
    (void)in_sizes; (void)n_in; (void)out_size;
    const float* z  = (const float*)d_in[0];
    const float* cb = (const float*)d_in[1];
    float* out      = (float*)d_out;
    float* q_out    = out;
    float* zq_out   = out + (size_t)65536 * 1024;
    float* loss_out = zq_out + (size_t)65536 * 64;

    vq_prep<<<128, 256>>>(cb);
    vq_main<<<65536 / BM, THREADS>>>(z, cb, q_out, zq_out);
    vq_finalize<<<1, 1>>>(loss_out);
}

// round 5
// speedup vs baseline: 1.3911x; 1.3911x over previous
#include <cuda_runtime.h>
#include <cstdint>

#define BM      32
#define THREADS 512
#define NWARP   16
#define EPS     0.05f
#define MAXCAND 512

__device__ float  g_bfrag[128 * 8 * 32 * 2];  // [ntg][kk][lane]{b0,b1} tf32 of -2e
__device__ float  g_wn1[1024];                // ||e_c||^2 + 1
__device__ double g_loss;

__device__ __forceinline__ uint32_t tf32_rna(float v) {
    uint32_t u; asm("cvt.rna.tf32.f32 %0, %1;" : "=r"(u) : "f"(v));
    return u;
}
__device__ __forceinline__ float rcpf(float x) {
    float r; asm("rcp.approx.f32 %0, %1;" : "=f"(r) : "f"(x)); return r;
}
__device__ __forceinline__ unsigned int ordered_u32(float f) {
    unsigned int u = __float_as_uint(f);
    return (u & 0x80000000u) ? ~u : (u | 0x80000000u);
}
__device__ __forceinline__ void mma_tf32(float* d, const uint32_t* a,
                                         uint32_t b0, uint32_t b1) {
    asm volatile(
        "mma.sync.aligned.m16n8k8.row.col.f32.tf32.tf32.f32 "
        "{%0,%1,%2,%3}, {%4,%5,%6,%7}, {%8,%9}, {%0,%1,%2,%3};"
        : "+f"(d[0]), "+f"(d[1]), "+f"(d[2]), "+f"(d[3])
        : "r"(a[0]), "r"(a[1]), "r"(a[2]), "r"(a[3]), "r"(b0), "r"(b1));
}

// ---------------------------------------------------------------------------
// Prep: block ntg stages 8 codebook rows -> wn1 + tf32 B fragments (hi only)
// ---------------------------------------------------------------------------
__global__ void vq_prep(const float* __restrict__ cb) {
    __shared__ float rows[8 * 64];
    const int tid = threadIdx.x;
    const int ntg = blockIdx.x;
    if (ntg == 0 && tid == 0) g_loss = 0.0;
    ((float2*)rows)[tid] = ((const float2*)(cb + (size_t)ntg * 512))[tid];
    __syncthreads();
    if (tid < 8) {
        float s = 0.f;
        const float* r = rows + tid * 64;
#pragma unroll 16
        for (int k = 0; k < 64; k++) { float v = r[k]; s += v * v; }
        g_wn1[ntg * 8 + tid] = s + 1.f;
    }
    const int lane = tid & 31;
    const int kk   = tid >> 5;
    const int g = lane >> 2, tq = lane & 3;
    const int k0 = kk * 8 + tq;
    float v0 = -2.f * rows[g * 64 + k0];
    float v1 = -2.f * rows[g * 64 + k0 + 4];
    float2 o;
    o.x = __uint_as_float(tf32_rna(v0));
    o.y = __uint_as_float(tf32_rna(v1));
    ((float2*)g_bfrag)[(size_t)ntg * 256 + tid] = o;
}

// ---------------------------------------------------------------------------
// Main fused kernel: 32 rows x 1024 cols/CTA; 1-pass tf32 GEMM + exact refine
// ---------------------------------------------------------------------------
__global__ void __launch_bounds__(THREADS, 1)
vq_main(const float* __restrict__ z, const float* __restrict__ cb,
        float* __restrict__ q_out, float* __restrict__ zq_out) {
    __shared__ float z_s[32 * 64];
    __shared__ float ahi_s[512 * 4];          // A frags [kk*2+mt][lane][4]
    __shared__ float wn_s[1024];
    __shared__ float zn2_s[32];
    __shared__ float inv_s[32];
    __shared__ float thr_s[32];               // q-threshold per row
    __shared__ int   bc_s[32];
    __shared__ float rs_p[NWARP][32];
    __shared__ float qm_p[NWARP][32];
    __shared__ unsigned long long rowbest[32];
    __shared__ unsigned int cand_s[MAXCAND];
    __shared__ int ncand_s;

    const int tid  = threadIdx.x;
    const int wid  = tid >> 5;
    const int lane = tid & 31;
    const int g    = lane >> 2;
    const int tq   = lane & 3;
    const int r0   = blockIdx.x * BM;

    ((float4*)z_s)[tid] = ((const float4*)(z + (size_t)r0 * 64))[tid];
    wn_s[tid]       = g_wn1[tid];
    wn_s[tid + 512] = g_wn1[tid + 512];
    __syncthreads();

    // A fragments (tf32 hi only): slot s -> kk=s>>6, mt=(s>>5)&1, lane=s&31
    {
        int s_ = tid;
        int kk = s_ >> 6, mt = (s_ >> 5) & 1, ln = s_ & 31;
        int gg = ln >> 2, qq = ln & 3;
        int rr = mt * 16 + gg, k0 = kk * 8 + qq;
        float4 hv;
        hv.x = __uint_as_float(tf32_rna(z_s[rr * 64 + k0]));
        hv.y = __uint_as_float(tf32_rna(z_s[(rr + 8) * 64 + k0]));
        hv.z = __uint_as_float(tf32_rna(z_s[rr * 64 + k0 + 4]));
        hv.w = __uint_as_float(tf32_rna(z_s[(rr + 8) * 64 + k0 + 4]));
        ((float4*)ahi_s)[s_] = hv;
    }
    if (tid < 32) {
        float s = 0.f;
        const float* zr = z_s + tid * 64;
#pragma unroll 16
        for (int k = 0; k < 64; k++) { float v = zr[k]; s += v * v; }
        zn2_s[tid] = s;
        rowbest[tid] = 0ull;
    }
    if (tid == 0) ncand_s = 0;
    __syncthreads();

    // ---- single-pass tf32 GEMM ----
    float acc[2][8][4];
#pragma unroll
    for (int mt = 0; mt < 2; mt++)
#pragma unroll
        for (int nt = 0; nt < 8; nt++)
#pragma unroll
            for (int r = 0; r < 4; r++) acc[mt][nt][r] = 0.f;

    const float2* bb = (const float2*)g_bfrag + (size_t)(wid * 8) * 256 + lane;
    float2 bf[8];
#pragma unroll
    for (int nt = 0; nt < 8; nt++) bf[nt] = __ldg(bb + nt * 256);

#pragma unroll 1
    for (int kk = 0; kk < 8; kk++) {
        uint32_t ah[2][4];
#pragma unroll
        for (int mt = 0; mt < 2; mt++) {
            float4 h = ((const float4*)ahi_s)[(kk * 2 + mt) * 32 + lane];
            ah[mt][0] = __float_as_uint(h.x); ah[mt][1] = __float_as_uint(h.y);
            ah[mt][2] = __float_as_uint(h.z); ah[mt][3] = __float_as_uint(h.w);
        }
#pragma unroll
        for (int nt = 0; nt < 8; nt++) {
            float2 b = bf[nt];
            if (kk < 7) bf[nt] = __ldg(bb + nt * 256 + (kk + 1) * 32);
            uint32_t b0 = __float_as_uint(b.x), b1 = __float_as_uint(b.y);
            mma_tf32(acc[0][nt], ah[0], b0, b1);
            mma_tf32(acc[1][nt], ah[1], b0, b1);
        }
    }

    // ---- pass 1: qv = rcp(S), rowsum, row-min q (== row-max S) ----
    float rs[4]   = {0.f, 0.f, 0.f, 0.f};
    float qmin[4] = {3.4e38f, 3.4e38f, 3.4e38f, 3.4e38f};
    const int wc0 = wid * 64;

#pragma unroll
    for (int mt = 0; mt < 2; mt++) {
#pragma unroll
        for (int h = 0; h < 2; h++) {
            int rloc = mt * 16 + g + h * 8;
            float zn = zn2_s[rloc];
#pragma unroll
            for (int nt = 0; nt < 8; nt++) {
#pragma unroll
                for (int p = 0; p < 2; p++) {
                    int c  = wc0 + nt * 8 + tq * 2 + p;
                    float S  = acc[mt][nt][h * 2 + p] + zn + wn_s[c];
                    float qv = rcpf(S);
                    acc[mt][nt][h * 2 + p] = qv;
                    int ri = mt * 2 + h;
                    rs[ri] += qv;
                    qmin[ri] = fminf(qmin[ri], qv);
                }
            }
        }
    }
#pragma unroll
    for (int m = 1; m <= 2; m <<= 1) {
#pragma unroll
        for (int r = 0; r < 4; r++) {
            rs[r]  += __shfl_xor_sync(0xFFFFFFFFu, rs[r], m);
            qmin[r] = fminf(qmin[r], __shfl_xor_sync(0xFFFFFFFFu, qmin[r], m));
        }
    }
    if (tq == 0) {
#pragma unroll
        for (int r = 0; r < 4; r++) {
            int rloc = (r >> 1) * 16 + g + (r & 1) * 8;
            rs_p[wid][rloc] = rs[r];
            qm_p[wid][rloc] = qmin[r];
        }
    }
    __syncthreads();
    if (tid < 32) {
        float s = 0.f, qm = 3.4e38f;
#pragma unroll
        for (int w = 0; w < NWARP; w++) {
            s += rs_p[w][tid];
            qm = fminf(qm, qm_p[w][tid]);
        }
        inv_s[tid] = 1.0f / s;
        float Smax = 1.0f / qm;           // approx max S for this row
        thr_s[tid] = 1.0f / (Smax - EPS); // candidate iff qv <= thr
    }
    __syncthreads();

    // ---- candidate scan (qv small <=> S large <=> d large) ----
#pragma unroll
    for (int mt = 0; mt < 2; mt++) {
#pragma unroll
        for (int h = 0; h < 2; h++) {
            int rloc = mt * 16 + g + h * 8;
            float thr = thr_s[rloc];
#pragma unroll
            for (int nt = 0; nt < 8; nt++) {
#pragma unroll
                for (int p = 0; p < 2; p++) {
                    if (acc[mt][nt][h * 2 + p] <= thr) {
                        int c = wc0 + nt * 8 + tq * 2 + p;
                        int i = atomicAdd(&ncand_s, 1);
                        if (i < MAXCAND)
                            cand_s[i] = ((unsigned int)rloc << 16) | (unsigned int)c;
                    }
                }
            }
        }
    }
    __syncthreads();

    // ---- exact fp32 refine of candidates (one warp per candidate) ----
    {
        int nc = ncand_s < MAXCAND ? ncand_s : MAXCAND;
        for (int i = wid; i < nc; i += NWARP) {
            unsigned int pc = cand_s[i];
            int rr = pc >> 16, c = pc & 0xFFFF;
            float2 zv = ((const float2*)(z_s + rr * 64))[lane];
            float2 ev = __ldg((const float2*)(cb + (size_t)c * 64) + lane);
            float p = zv.x * ev.x + zv.y * ev.y;
#pragma unroll
            for (int m = 16; m > 0; m >>= 1)
                p += __shfl_xor_sync(0xFFFFFFFFu, p, m);
            if (lane == 0) {
                float d = zn2_s[rr] + (wn_s[c] - 1.0f) - 2.f * p;
                unsigned long long key =
                    ((unsigned long long)ordered_u32(d) << 32) |
                    (unsigned long long)(0xFFFFFFFFu - (unsigned int)c);
                atomicMax(&rowbest[rr], key);
            }
        }
    }
    __syncthreads();
    if (tid < 32)
        bc_s[tid] = (int)(0xFFFFFFFFu -
                          (unsigned int)(rowbest[tid] & 0xFFFFFFFFull));
    __syncthreads();

    // ---- store normalized q ----
#pragma unroll
    for (int mt = 0; mt < 2; mt++) {
#pragma unroll
        for (int h = 0; h < 2; h++) {
            int rloc = mt * 16 + g + h * 8;
            float inv = inv_s[rloc];
            float* base = q_out + (size_t)(r0 + rloc) * 1024 + wc0 + tq * 2;
#pragma unroll
            for (int nt = 0; nt < 8; nt++) {
                float2 v;
                v.x = acc[mt][nt][h * 2 + 0] * inv;
                v.y = acc[mt][nt][h * 2 + 1] * inv;
                *(float2*)(base + nt * 8) = v;
            }
        }
    }

    // ---- gather z_q, store, loss ----
    float lp;
    {
        int rr = tid >> 4, j4 = tid & 15;
        int cbest = bc_s[rr];
        float4 e  = ((const float4*)(cb + (size_t)cbest * 64))[j4];
        float4 zv = ((const float4*)z_s)[rr * 16 + j4];
        ((float4*)(zq_out + (size_t)(r0 + rr) * 64))[j4] = e;
        float dx = e.x - zv.x, dy = e.y - zv.y,
              dz = e.z - zv.z, dw = e.w - zv.w;
        lp = dx * dx + dy * dy + dz * dz + dw * dw;
    }
#pragma unroll
    for (int m = 16; m > 0; m >>= 1)
        lp += __shfl_xor_sync(0xFFFFFFFFu, lp, m);
    float* red = &rs_p[0][0];
    if (lane == 0) red[wid] = lp;
    __syncthreads();
    if (tid < 16) {
        float v = red[tid];
#pragma unroll
        for (int m = 8; m > 0; m >>= 1)
            v += __shfl_xor_sync(0x0000FFFFu, v, m);
        if (tid == 0) atomicAdd(&g_loss, (double)v);
    }
}

__global__ void vq_finalize(float* __restrict__ loss_out) {
    loss_out[0] = (float)(1.25 * g_loss / (65536.0 * 64.0));
}

extern "C" void kernel_launch(void* const* d_in, const int* in_sizes, int n_in,
                              void* d_out, int out_size) {
    (void)in_sizes; (void)n_in; (void)out_size;
    const float* z  = (const float*)d_in[0];
    const float* cb = (const float*)d_in[1];
    float* out      = (float*)d_out;
    float* q_out    = out;
    float* zq_out   = out + (size_t)65536 * 1024;
    float* loss_out = zq_out + (size_t)65536 * 64;

    vq_prep<<<128, 256>>>(cb);
    vq_main<<<65536 / BM, THREADS>>>(z, cb, q_out, zq_out);
    vq_finalize<<<1, 1>>>(loss_out);
}

// round 6
// speedup vs baseline: 1.4876x; 1.0694x over previous
#include <cuda_runtime.h>
#include <cuda_fp16.h>
#include <cstdint>

#define BM      32
#define THREADS 512
#define NWARP   16
#define EPS     0.10f
#define MAXCAND 512

__device__ uint2  g_bfrag[128 * 4 * 32];   // [ntg][kc][lane]{b0,b1} fp16 of -2e
__device__ float  g_wn1[1024];             // ||e_c||^2 + 1
__device__ double g_loss;

__device__ __forceinline__ float rcpf(float x) {
    float r; asm("rcp.approx.f32 %0, %1;" : "=f"(r) : "f"(x)); return r;
}
__device__ __forceinline__ unsigned int ordered_u32(float f) {
    unsigned int u = __float_as_uint(f);
    return (u & 0x80000000u) ? ~u : (u | 0x80000000u);
}
__device__ __forceinline__ void mma_fp16(float* d, const uint32_t* a,
                                         uint32_t b0, uint32_t b1) {
    asm volatile(
        "mma.sync.aligned.m16n8k16.row.col.f32.f16.f16.f32 "
        "{%0,%1,%2,%3}, {%4,%5,%6,%7}, {%8,%9}, {%0,%1,%2,%3};"
        : "+f"(d[0]), "+f"(d[1]), "+f"(d[2]), "+f"(d[3])
        : "r"(a[0]), "r"(a[1]), "r"(a[2]), "r"(a[3]), "r"(b0), "r"(b1));
}
__device__ __forceinline__ uint32_t h2pack(float a, float b) {
    __half2 h = __floats2half2_rn(a, b);
    return *(uint32_t*)&h;
}

// ---------------------------------------------------------------------------
// Prep: block ntg stages 8 codebook rows -> wn1 + fp16 B fragments (m16n8k16)
// ---------------------------------------------------------------------------
__global__ void vq_prep(const float* __restrict__ cb) {
    __shared__ float rows[8 * 64];
    const int tid = threadIdx.x;
    const int ntg = blockIdx.x;
    if (ntg == 0 && tid == 0) g_loss = 0.0;
    ((float2*)rows)[tid] = ((const float2*)(cb + (size_t)ntg * 512))[tid];
    __syncthreads();
    if (tid < 8) {
        float s = 0.f;
        const float* r = rows + tid * 64;
#pragma unroll 16
        for (int k = 0; k < 64; k++) { float v = r[k]; s += v * v; }
        g_wn1[ntg * 8 + tid] = s + 1.f;
    }
    if (tid < 128) {
        const int lane = tid & 31;
        const int kc   = tid >> 5;          // 0..3
        const int g = lane >> 2, tq = lane & 3;
        const int k0 = kc * 16 + tq * 2;
        const float* r = rows + g * 64;
        uint2 o;
        o.x = h2pack(-2.f * r[k0],     -2.f * r[k0 + 1]);
        o.y = h2pack(-2.f * r[k0 + 8], -2.f * r[k0 + 9]);
        g_bfrag[(size_t)ntg * 128 + tid] = o;
    }
}

// ---------------------------------------------------------------------------
// Main fused kernel: 32 rows x 1024 cols/CTA; 1-pass fp16 GEMM + exact refine
// ---------------------------------------------------------------------------
__global__ void __launch_bounds__(THREADS, 1)
vq_main(const float* __restrict__ z, const float* __restrict__ cb,
        float* __restrict__ q_out, float* __restrict__ zq_out) {
    __shared__ float z_s[32 * 64];
    __shared__ uint4 af_s[256];               // A frags [kc*2+mt][lane]
    __shared__ float wn_s[1024];
    __shared__ float zn2_s[32];
    __shared__ float inv_s[32];
    __shared__ float thr_s[32];
    __shared__ int   bc_s[32];
    __shared__ float rs_p[NWARP][32];
    __shared__ float qm_p[NWARP][32];
    __shared__ unsigned long long rowbest[32];
    __shared__ unsigned int cand_s[MAXCAND];
    __shared__ int ncand_s;

    const int tid  = threadIdx.x;
    const int wid  = tid >> 5;
    const int lane = tid & 31;
    const int g    = lane >> 2;
    const int tq   = lane & 3;
    const int r0   = blockIdx.x * BM;

    ((float4*)z_s)[tid] = ((const float4*)(z + (size_t)r0 * 64))[tid];
    wn_s[tid]       = g_wn1[tid];
    wn_s[tid + 512] = g_wn1[tid + 512];
    __syncthreads();

    // A fragments fp16: slot -> kc=slot>>6, mt=(slot>>5)&1, lane=slot&31
    if (tid < 256) {
        int slot = tid;
        int kc = slot >> 6, mt = (slot >> 5) & 1, ln = slot & 31;
        int gg = ln >> 2, qq = ln & 3;
        int rr = mt * 16 + gg, k0 = kc * 16 + qq * 2;
        const float* zr0 = z_s + rr * 64;
        const float* zr1 = z_s + (rr + 8) * 64;
        uint4 v;
        v.x = h2pack(zr0[k0],     zr0[k0 + 1]);
        v.y = h2pack(zr1[k0],     zr1[k0 + 1]);
        v.z = h2pack(zr0[k0 + 8], zr0[k0 + 9]);
        v.w = h2pack(zr1[k0 + 8], zr1[k0 + 9]);
        af_s[slot] = v;
    }
    if (tid < 32) {
        float s = 0.f;
        const float* zr = z_s + tid * 64;
#pragma unroll 16
        for (int k = 0; k < 64; k++) { float v = zr[k]; s += v * v; }
        zn2_s[tid] = s;
        rowbest[tid] = 0ull;
    }
    if (tid == 0) ncand_s = 0;
    __syncthreads();

    // ---- single-pass fp16 GEMM: 64 MMAs/warp ----
    float acc[2][8][4];
#pragma unroll
    for (int mt = 0; mt < 2; mt++)
#pragma unroll
        for (int nt = 0; nt < 8; nt++)
#pragma unroll
            for (int r = 0; r < 4; r++) acc[mt][nt][r] = 0.f;

    // frag (nt, kc) at bb + nt*128 + kc*32
    const uint2* bb = g_bfrag + (size_t)(wid * 8) * 128 + lane;
    uint2 bf[8];
#pragma unroll
    for (int nt = 0; nt < 8; nt++) bf[nt] = __ldg(bb + nt * 128);

#pragma unroll
    for (int kc = 0; kc < 4; kc++) {
        uint4 a0 = af_s[(kc * 2 + 0) * 32 + lane];
        uint4 a1 = af_s[(kc * 2 + 1) * 32 + lane];
        uint32_t ah0[4] = {a0.x, a0.y, a0.z, a0.w};
        uint32_t ah1[4] = {a1.x, a1.y, a1.z, a1.w};
#pragma unroll
        for (int nt = 0; nt < 8; nt++) {
            uint2 b = bf[nt];
            if (kc < 3) bf[nt] = __ldg(bb + nt * 128 + (kc + 1) * 32);
            mma_fp16(acc[0][nt], ah0, b.x, b.y);
            mma_fp16(acc[1][nt], ah1, b.x, b.y);
        }
    }

    // ---- pass 1: qv = rcp(S), rowsum, row-min q (== row-max S) ----
    float rs[4]   = {0.f, 0.f, 0.f, 0.f};
    float qmin[4] = {3.4e38f, 3.4e38f, 3.4e38f, 3.4e38f};
    const int wc0 = wid * 64;

#pragma unroll
    for (int mt = 0; mt < 2; mt++) {
#pragma unroll
        for (int h = 0; h < 2; h++) {
            int rloc = mt * 16 + g + h * 8;
            float zn = zn2_s[rloc];
#pragma unroll
            for (int nt = 0; nt < 8; nt++) {
#pragma unroll
                for (int p = 0; p < 2; p++) {
                    int c  = wc0 + nt * 8 + tq * 2 + p;
                    float S  = acc[mt][nt][h * 2 + p] + zn + wn_s[c];
                    float qv = rcpf(S);
                    acc[mt][nt][h * 2 + p] = qv;
                    int ri = mt * 2 + h;
                    rs[ri] += qv;
                    qmin[ri] = fminf(qmin[ri], qv);
                }
            }
        }
    }
#pragma unroll
    for (int m = 1; m <= 2; m <<= 1) {
#pragma unroll
        for (int r = 0; r < 4; r++) {
            rs[r]  += __shfl_xor_sync(0xFFFFFFFFu, rs[r], m);
            qmin[r] = fminf(qmin[r], __shfl_xor_sync(0xFFFFFFFFu, qmin[r], m));
        }
    }
    if (tq == 0) {
#pragma unroll
        for (int r = 0; r < 4; r++) {
            int rloc = (r >> 1) * 16 + g + (r & 1) * 8;
            rs_p[wid][rloc] = rs[r];
            qm_p[wid][rloc] = qmin[r];
        }
    }
    __syncthreads();
    if (tid < 32) {
        float s = 0.f, qm = 3.4e38f;
#pragma unroll
        for (int w = 0; w < NWARP; w++) {
            s += rs_p[w][tid];
            qm = fminf(qm, qm_p[w][tid]);
        }
        inv_s[tid] = 1.0f / s;
        float Smax = 1.0f / qm;
        thr_s[tid] = 1.0f / (Smax - EPS);
    }
    __syncthreads();

    // ---- candidate scan ----
#pragma unroll
    for (int mt = 0; mt < 2; mt++) {
#pragma unroll
        for (int h = 0; h < 2; h++) {
            int rloc = mt * 16 + g + h * 8;
            float thr = thr_s[rloc];
#pragma unroll
            for (int nt = 0; nt < 8; nt++) {
#pragma unroll
                for (int p = 0; p < 2; p++) {
                    if (acc[mt][nt][h * 2 + p] <= thr) {
                        int c = wc0 + nt * 8 + tq * 2 + p;
                        int i = atomicAdd(&ncand_s, 1);
                        if (i < MAXCAND)
                            cand_s[i] = ((unsigned int)rloc << 16) | (unsigned int)c;
                    }
                }
            }
        }
    }
    __syncthreads();

    // ---- exact fp32 refine (one warp per candidate) ----
    {
        int nc = ncand_s < MAXCAND ? ncand_s : MAXCAND;
        for (int i = wid; i < nc; i += NWARP) {
            unsigned int pc = cand_s[i];
            int rr = pc >> 16, c = pc & 0xFFFF;
            float2 zv = ((const float2*)(z_s + rr * 64))[lane];
            float2 ev = __ldg((const float2*)(cb + (size_t)c * 64) + lane);
            float p = zv.x * ev.x + zv.y * ev.y;
#pragma unroll
            for (int m = 16; m > 0; m >>= 1)
                p += __shfl_xor_sync(0xFFFFFFFFu, p, m);
            if (lane == 0) {
                float d = zn2_s[rr] + (wn_s[c] - 1.0f) - 2.f * p;
                unsigned long long key =
                    ((unsigned long long)ordered_u32(d) << 32) |
                    (unsigned long long)(0xFFFFFFFFu - (unsigned int)c);
                atomicMax(&rowbest[rr], key);
            }
        }
    }
    __syncthreads();
    if (tid < 32)
        bc_s[tid] = (int)(0xFFFFFFFFu -
                          (unsigned int)(rowbest[tid] & 0xFFFFFFFFull));
    __syncthreads();

    // ---- store normalized q ----
#pragma unroll
    for (int mt = 0; mt < 2; mt++) {
#pragma unroll
        for (int h = 0; h < 2; h++) {
            int rloc = mt * 16 + g + h * 8;
            float inv = inv_s[rloc];
            float* base = q_out + (size_t)(r0 + rloc) * 1024 + wc0 + tq * 2;
#pragma unroll
            for (int nt = 0; nt < 8; nt++) {
                float2 v;
                v.x = acc[mt][nt][h * 2 + 0] * inv;
                v.y = acc[mt][nt][h * 2 + 1] * inv;
                *(float2*)(base + nt * 8) = v;
            }
        }
    }

    // ---- gather z_q, store, loss ----
    float lp;
    {
        int rr = tid >> 4, j4 = tid & 15;
        int cbest = bc_s[rr];
        float4 e  = ((const float4*)(cb + (size_t)cbest * 64))[j4];
        float4 zv = ((const float4*)z_s)[rr * 16 + j4];
        ((float4*)(zq_out + (size_t)(r0 + rr) * 64))[j4] = e;
        float dx = e.x - zv.x, dy = e.y - zv.y,
              dz = e.z - zv.z, dw = e.w - zv.w;
        lp = dx * dx + dy * dy + dz * dz + dw * dw;
    }
#pragma unroll
    for (int m = 16; m > 0; m >>= 1)
        lp += __shfl_xor_sync(0xFFFFFFFFu, lp, m);
    float* red = &rs_p[0][0];
    if (lane == 0) red[wid] = lp;
    __syncthreads();
    if (tid < 16) {
        float v = red[tid];
#pragma unroll
        for (int m = 8; m > 0; m >>= 1)
            v += __shfl_xor_sync(0x0000FFFFu, v, m);
        if (tid == 0) atomicAdd(&g_loss, (double)v);
    }
}

__global__ void vq_finalize(float* __restrict__ loss_out) {
    loss_out[0] = (float)(1.25 * g_loss / (65536.0 * 64.0));
}

extern "C" void kernel_launch(void* const* d_in, const int* in_sizes, int n_in,
                              void* d_out, int out_size) {
    (void)in_sizes; (void)n_in; (void)out_size;
    const float* z  = (const float*)d_in[0];
    const float* cb = (const float*)d_in[1];
    float* out      = (float*)d_out;
    float* q_out    = out;
    float* zq_out   = out + (size_t)65536 * 1024;
    float* loss_out = zq_out + (size_t)65536 * 64;

    vq_prep<<<128, 256>>>(cb);
    vq_main<<<65536 / BM, THREADS>>>(z, cb, q_out, zq_out);
    vq_finalize<<<1, 1>>>(loss_out);
}

// round 7
// speedup vs baseline: 1.7038x; 1.1454x over previous
#include <cuda_runtime.h>
#include <cuda_fp16.h>
#include <cstdint>

#define BM      16
#define THREADS 256
#define NWARP   8
#define EPS     0.10f
#define MAXCAND 256

__device__ uint2  g_bfrag[128 * 4 * 32];   // [ntg][kc][lane]{b0,b1} fp16 of -2e
__device__ float  g_wn1[1024];             // ||e_c||^2 + 1
__device__ double g_loss;

__device__ __forceinline__ float rcpf(float x) {
    float r; asm("rcp.approx.f32 %0, %1;" : "=f"(r) : "f"(x)); return r;
}
__device__ __forceinline__ unsigned int ordered_u32(float f) {
    unsigned int u = __float_as_uint(f);
    return (u & 0x80000000u) ? ~u : (u | 0x80000000u);
}
__device__ __forceinline__ void mma_fp16(float* d, const uint32_t* a,
                                         uint32_t b0, uint32_t b1) {
    asm volatile(
        "mma.sync.aligned.m16n8k16.row.col.f32.f16.f16.f32 "
        "{%0,%1,%2,%3}, {%4,%5,%6,%7}, {%8,%9}, {%0,%1,%2,%3};"
        : "+f"(d[0]), "+f"(d[1]), "+f"(d[2]), "+f"(d[3])
        : "r"(a[0]), "r"(a[1]), "r"(a[2]), "r"(a[3]), "r"(b0), "r"(b1));
}
__device__ __forceinline__ uint32_t h2pack(float a, float b) {
    __half2 h = __floats2half2_rn(a, b);
    return *(uint32_t*)&h;
}

// ---------------------------------------------------------------------------
// Prep: block ntg stages 8 codebook rows -> wn1 + fp16 B fragments (m16n8k16)
// ---------------------------------------------------------------------------
__global__ void vq_prep(const float* __restrict__ cb) {
    __shared__ float rows[8 * 64];
    const int tid = threadIdx.x;
    const int ntg = blockIdx.x;
    if (ntg == 0 && tid == 0) g_loss = 0.0;
    ((float2*)rows)[tid] = ((const float2*)(cb + (size_t)ntg * 512))[tid];
    __syncthreads();
    if (tid < 8) {
        float s = 0.f;
        const float* r = rows + tid * 64;
#pragma unroll 16
        for (int k = 0; k < 64; k++) { float v = r[k]; s += v * v; }
        g_wn1[ntg * 8 + tid] = s + 1.f;
    }
    if (tid < 128) {
        const int lane = tid & 31;
        const int kc   = tid >> 5;          // 0..3
        const int g = lane >> 2, tq = lane & 3;
        const int k0 = kc * 16 + tq * 2;
        const float* r = rows + g * 64;
        uint2 o;
        o.x = h2pack(-2.f * r[k0],     -2.f * r[k0 + 1]);
        o.y = h2pack(-2.f * r[k0 + 8], -2.f * r[k0 + 9]);
        g_bfrag[(size_t)ntg * 128 + tid] = o;
    }
}

// ---------------------------------------------------------------------------
// Main: 16 rows x 1024 cols/CTA, 8 warps x (16x128 slab), occ 2/SM
// ---------------------------------------------------------------------------
__global__ void __launch_bounds__(THREADS, 2)
vq_main(const float* __restrict__ z, const float* __restrict__ cb,
        float* __restrict__ q_out, float* __restrict__ zq_out) {
    __shared__ float z_s[16 * 64];
    __shared__ uint4 af_s[128];               // A frags [kc][lane]
    __shared__ float wn_s[1024];
    __shared__ float zn2_s[16];
    __shared__ float inv_s[16];
    __shared__ float thr_s[16];
    __shared__ int   bc_s[16];
    __shared__ float rs_p[NWARP][16];
    __shared__ float qm_p[NWARP][16];
    __shared__ unsigned long long rowbest[16];
    __shared__ unsigned int cand_s[MAXCAND];
    __shared__ int ncand_s;

    const int tid  = threadIdx.x;
    const int wid  = tid >> 5;
    const int lane = tid & 31;
    const int g    = lane >> 2;
    const int tq   = lane & 3;
    const int r0   = blockIdx.x * BM;

    ((float4*)z_s)[tid] = ((const float4*)(z + (size_t)r0 * 64))[tid];
    ((float4*)wn_s)[tid] = ((const float4*)g_wn1)[tid];
    __syncthreads();

    // A fragments fp16 (single m-tile of 16 rows): slot = kc*32 + lane
    if (tid < 128) {
        int kc = tid >> 5, ln = tid & 31;
        int gg = ln >> 2, qq = ln & 3;
        int k0 = kc * 16 + qq * 2;
        const float* zr0 = z_s + gg * 64;
        const float* zr1 = z_s + (gg + 8) * 64;
        uint4 v;
        v.x = h2pack(zr0[k0],     zr0[k0 + 1]);
        v.y = h2pack(zr1[k0],     zr1[k0 + 1]);
        v.z = h2pack(zr0[k0 + 8], zr0[k0 + 9]);
        v.w = h2pack(zr1[k0 + 8], zr1[k0 + 9]);
        af_s[tid] = v;
    }
    if (tid < 16) {
        float s = 0.f;
        const float* zr = z_s + tid * 64;
#pragma unroll 16
        for (int k = 0; k < 64; k++) { float v = zr[k]; s += v * v; }
        zn2_s[tid] = s;
        rowbest[tid] = 0ull;
    }
    if (tid == 0) ncand_s = 0;
    __syncthreads();

    // ---- GEMM: warp wid owns cols wid*128..+127; 64 MMAs/warp ----
    float acc[16][4];
#pragma unroll
    for (int nt = 0; nt < 16; nt++)
#pragma unroll
        for (int r = 0; r < 4; r++) acc[nt][r] = 0.f;

    const uint2* bb = g_bfrag + (size_t)(wid * 16) * 128 + lane;

#pragma unroll
    for (int half = 0; half < 2; half++) {
        uint2 bf[8];
#pragma unroll
        for (int j = 0; j < 8; j++) bf[j] = __ldg(bb + (half * 8 + j) * 128);
#pragma unroll
        for (int kc = 0; kc < 4; kc++) {
            uint4 a = af_s[kc * 32 + lane];
            uint32_t ar[4] = {a.x, a.y, a.z, a.w};
#pragma unroll
            for (int j = 0; j < 8; j++) {
                uint2 b = bf[j];
                if (kc < 3) bf[j] = __ldg(bb + (half * 8 + j) * 128 + (kc + 1) * 32);
                mma_fp16(acc[half * 8 + j], ar, b.x, b.y);
            }
        }
    }

    // ---- pass 1: qv = rcp(S), rowsum, row-min q ----
    float rs[2]   = {0.f, 0.f};
    float qmin[2] = {3.4e38f, 3.4e38f};
    const int wc0 = wid * 128;

#pragma unroll
    for (int h = 0; h < 2; h++) {
        int rloc = g + h * 8;
        float zn = zn2_s[rloc];
#pragma unroll
        for (int nt = 0; nt < 16; nt++) {
#pragma unroll
            for (int p = 0; p < 2; p++) {
                int c  = wc0 + nt * 8 + tq * 2 + p;
                float S  = acc[nt][h * 2 + p] + zn + wn_s[c];
                float qv = rcpf(S);
                acc[nt][h * 2 + p] = qv;
                rs[h] += qv;
                qmin[h] = fminf(qmin[h], qv);
            }
        }
    }
#pragma unroll
    for (int m = 1; m <= 2; m <<= 1) {
#pragma unroll
        for (int h = 0; h < 2; h++) {
            rs[h]  += __shfl_xor_sync(0xFFFFFFFFu, rs[h], m);
            qmin[h] = fminf(qmin[h], __shfl_xor_sync(0xFFFFFFFFu, qmin[h], m));
        }
    }
    if (tq == 0) {
#pragma unroll
        for (int h = 0; h < 2; h++) {
            rs_p[wid][g + h * 8] = rs[h];
            qm_p[wid][g + h * 8] = qmin[h];
        }
    }
    __syncthreads();
    if (tid < 16) {
        float s = 0.f, qm = 3.4e38f;
#pragma unroll
        for (int w = 0; w < NWARP; w++) {
            s += rs_p[w][tid];
            qm = fminf(qm, qm_p[w][tid]);
        }
        inv_s[tid] = 1.0f / s;
        float Smax = 1.0f / qm;
        thr_s[tid] = 1.0f / (Smax - EPS);
    }
    __syncthreads();

    // ---- candidate scan ----
#pragma unroll
    for (int h = 0; h < 2; h++) {
        int rloc = g + h * 8;
        float thr = thr_s[rloc];
#pragma unroll
        for (int nt = 0; nt < 16; nt++) {
#pragma unroll
            for (int p = 0; p < 2; p++) {
                if (acc[nt][h * 2 + p] <= thr) {
                    int c = wc0 + nt * 8 + tq * 2 + p;
                    int i = atomicAdd(&ncand_s, 1);
                    if (i < MAXCAND)
                        cand_s[i] = ((unsigned int)rloc << 16) | (unsigned int)c;
                }
            }
        }
    }
    __syncthreads();

    // ---- exact fp32 refine (one warp per candidate) ----
    {
        int nc = ncand_s < MAXCAND ? ncand_s : MAXCAND;
        for (int i = wid; i < nc; i += NWARP) {
            unsigned int pc = cand_s[i];
            int rr = pc >> 16, c = pc & 0xFFFF;
            float2 zv = ((const float2*)(z_s + rr * 64))[lane];
            float2 ev = __ldg((const float2*)(cb + (size_t)c * 64) + lane);
            float p = zv.x * ev.x + zv.y * ev.y;
#pragma unroll
            for (int m = 16; m > 0; m >>= 1)
                p += __shfl_xor_sync(0xFFFFFFFFu, p, m);
            if (lane == 0) {
                float d = zn2_s[rr] + (wn_s[c] - 1.0f) - 2.f * p;
                unsigned long long key =
                    ((unsigned long long)ordered_u32(d) << 32) |
                    (unsigned long long)(0xFFFFFFFFu - (unsigned int)c);
                atomicMax(&rowbest[rr], key);
            }
        }
    }
    __syncthreads();
    if (tid < 16)
        bc_s[tid] = (int)(0xFFFFFFFFu -
                          (unsigned int)(rowbest[tid] & 0xFFFFFFFFull));
    __syncthreads();

    // ---- store normalized q ----
#pragma unroll
    for (int h = 0; h < 2; h++) {
        int rloc = g + h * 8;
        float inv = inv_s[rloc];
        float* base = q_out + (size_t)(r0 + rloc) * 1024 + wc0 + tq * 2;
#pragma unroll
        for (int nt = 0; nt < 16; nt++) {
            float2 v;
            v.x = acc[nt][h * 2 + 0] * inv;
            v.y = acc[nt][h * 2 + 1] * inv;
            *(float2*)(base + nt * 8) = v;
        }
    }

    // ---- gather z_q, store, loss ----
    float lp;
    {
        int rr = tid >> 4, j4 = tid & 15;
        int cbest = bc_s[rr];
        float4 e  = ((const float4*)(cb + (size_t)cbest * 64))[j4];
        float4 zv = ((const float4*)z_s)[rr * 16 + j4];
        ((float4*)(zq_out + (size_t)(r0 + rr) * 64))[j4] = e;
        float dx = e.x - zv.x, dy = e.y - zv.y,
              dz = e.z - zv.z, dw = e.w - zv.w;
        lp = dx * dx + dy * dy + dz * dz + dw * dw;
    }
#pragma unroll
    for (int m = 16; m > 0; m >>= 1)
        lp += __shfl_xor_sync(0xFFFFFFFFu, lp, m);
    float* red = &rs_p[0][0];
    if (lane == 0) red[wid] = lp;
    __syncthreads();
    if (tid < 8) {
        float v = red[tid];
#pragma unroll
        for (int m = 4; m > 0; m >>= 1)
            v += __shfl_xor_sync(0x000000FFu, v, m);
        if (tid == 0) atomicAdd(&g_loss, (double)v);
    }
}

__global__ void vq_finalize(float* __restrict__ loss_out) {
    loss_out[0] = (float)(1.25 * g_loss / (65536.0 * 64.0));
}

extern "C" void kernel_launch(void* const* d_in, const int* in_sizes, int n_in,
                              void* d_out, int out_size) {
    (void)in_sizes; (void)n_in; (void)out_size;
    const float* z  = (const float*)d_in[0];
    const float* cb = (const float*)d_in[1];
    float* out      = (float*)d_out;
    float* q_out    = out;
    float* zq_out   = out + (size_t)65536 * 1024;
    float* loss_out = zq_out + (size_t)65536 * 64;

    vq_prep<<<128, 256>>>(cb);
    vq_main<<<65536 / BM, THREADS>>>(z, cb, q_out, zq_out);
    vq_finalize<<<1, 1>>>(loss_out);
}